// round 3
// baseline (speedup 1.0000x reference)
#include <cuda_runtime.h>
#include <cuda_bf16.h>
#include <cstdint>

#define BATCH 8
#define NPTS  8192
#define NCTR  2048          // NPTS * 0.25
#define NSAMP 32
#define C0IN  67
#define C0    64
#define C1    64
#define C2    128
#define R2    0.25f         // radius^2

// ---------------- scratch (device globals; no allocation allowed) ----------------
__device__ int   g_ballidx[BATCH * NCTR * NSAMP];            // 2 MB
__device__ float g_F0[(size_t)BATCH * NPTS * C0];            // 16 MB, layout (b, j, o)

// ---------------- f32x2 packed helpers ----------------
__device__ __forceinline__ unsigned long long pk2(float lo, float hi) {
    unsigned long long r;
    asm("mov.b64 %0, {%1, %2};" : "=l"(r) : "f"(lo), "f"(hi));
    return r;
}
__device__ __forceinline__ unsigned long long pkb(float v) { return pk2(v, v); }
__device__ __forceinline__ void upk2(unsigned long long v, float& lo, float& hi) {
    asm("mov.b64 {%0, %1}, %2;" : "=f"(lo), "=f"(hi) : "l"(v));
}
#define F2FMA(d, a, b, c) asm("fma.rn.f32x2 %0, %1, %2, %3;" : "=l"(d) : "l"(a), "l"(b), "l"(c))
#define F2ADD(d, a, b)    asm("add.rn.f32x2 %0, %1, %2;"     : "=l"(d) : "l"(a), "l"(b))
#define F2MUL(d, a, b)    asm("mul.rn.f32x2 %0, %1, %2;"     : "=l"(d) : "l"(a), "l"(b))

// ---------------- cluster helpers ----------------
__device__ __forceinline__ unsigned ctarank() {
    unsigned r; asm("mov.u32 %0, %%cluster_ctarank;" : "=r"(r)); return r;
}
__device__ __forceinline__ unsigned smem_u32(const void* p) {
    return (unsigned)__cvta_generic_to_shared(p);
}
__device__ __forceinline__ unsigned mapa_u32(unsigned local, unsigned rank) {
    unsigned r;
    asm("mapa.shared::cluster.u32 %0, %1, %2;" : "=r"(r) : "r"(local), "r"(rank));
    return r;
}
__device__ __forceinline__ void st_cluster_v4(unsigned raddr, float x, float y, float z, float w) {
    asm volatile("st.shared::cluster.v4.b32 [%0], {%1,%2,%3,%4};"
                 :: "r"(raddr), "f"(x), "f"(y), "f"(z), "f"(w) : "memory");
}
__device__ __forceinline__ void st_cluster_rel_u64(unsigned raddr, unsigned long long v) {
    asm volatile("st.release.cluster.shared::cluster.b64 [%0], %1;"
                 :: "r"(raddr), "l"(v) : "memory");
}
__device__ __forceinline__ unsigned long long ld_acq_shared_u64(unsigned addr) {
    unsigned long long v;
    asm volatile("ld.acquire.cluster.shared.b64 %0, [%1];" : "=l"(v) : "r"(addr) : "memory");
    return v;
}
#define CLUSTER_SYNC() do { \
    asm volatile("barrier.cluster.arrive.aligned;" ::: "memory"); \
    asm volatile("barrier.cluster.wait.aligned;" ::: "memory");   \
} while (0)

// =====================================================================
// 1) FPS across an 8-CTA cluster per batch (64 SMs total).
//    256 threads/CTA, 4 points/thread. Per step: local reduce, DSMEM
//    all-to-all broadcast of (key, coords), local pick. 3-buffer slots.
// =====================================================================
#define FPS_CLUSTER 8
#define FPS_THREADS 256

__global__ void __launch_bounds__(FPS_THREADS, 1) __cluster_dims__(FPS_CLUSTER, 1, 1)
fps_kernel(const float* __restrict__ pos, float* __restrict__ new_xyz)
{
    const unsigned rank = ctarank();
    const int b = blockIdx.x / FPS_CLUSTER;
    const int t = threadIdx.x;
    const int lane = t & 31, w = t >> 5;
    const float* pb = pos + (size_t)b * NPTS * 3;
    const unsigned base = rank * 1024;

    // registers: 4 points, packed in pairs (local idx = j*256 + t, j=0..3)
    unsigned long long xp[2], yp[2], zp[2];
    float dm[4];
#pragma unroll
    for (int k = 0; k < 2; k++) {
        int l0 = base + t + (2 * k) * 256;
        int l1 = l0 + 256;
        xp[k] = pk2(pb[3 * l0 + 0], pb[3 * l1 + 0]);
        yp[k] = pk2(pb[3 * l0 + 1], pb[3 * l1 + 1]);
        zp[k] = pk2(pb[3 * l0 + 2], pb[3 * l1 + 2]);
        dm[2 * k] = 1e10f; dm[2 * k + 1] = 1e10f;
    }

    __shared__ unsigned long long s_key[3][FPS_CLUSTER];   // [buf][src rank]
    __shared__ float4 s_cord[3][FPS_CLUSTER];
    __shared__ unsigned s_wval[8], s_widx[8];
    __shared__ float s_wx[8], s_wy[8], s_wz[8];
    __shared__ float4 s_res;

    if (t < 3 * FPS_CLUSTER) ((unsigned long long*)s_key)[t] = 0ULL;
    __syncthreads();
    CLUSTER_SYNC();            // all slots zeroed cluster-wide before any send

    float cx = pb[0], cy = pb[1], cz = pb[2];
    if (rank == 0 && t == 0) {
        float* nz = new_xyz + (size_t)b * NCTR * 3;
        nz[0] = cx; nz[1] = cy; nz[2] = cz;
    }

    for (int s = 1; s < NCTR; ++s) {
        const int buf  = s % 3;
        const int buf2 = (s + 2) % 3;

        // ---- distance update (f32x2) + thread max ----
        const unsigned long long nx = pkb(-cx);
        const unsigned long long ny = pkb(-cy);
        const unsigned long long nz2 = pkb(-cz);
        float m = 0.0f;
#pragma unroll
        for (int k = 0; k < 2; k++) {
            unsigned long long dx, dy, dz, sq;
            F2ADD(dx, xp[k], nx);
            F2ADD(dy, yp[k], ny);
            F2ADD(dz, zp[k], nz2);
            F2MUL(sq, dx, dx);
            F2FMA(sq, dy, dy, sq);
            F2FMA(sq, dz, dz, sq);
            float lo, hi; upk2(sq, lo, hi);
            dm[2 * k]     = fminf(dm[2 * k], lo);
            dm[2 * k + 1] = fminf(dm[2 * k + 1], hi);
            m = fmaxf(m, dm[2 * k]);
            m = fmaxf(m, dm[2 * k + 1]);
        }

        // ---- warp reduce: max val, min idx on ties ----
        unsigned mb = __float_as_uint(m);
        unsigned wmax = __reduce_max_sync(0xffffffffu, mb);
        unsigned cand = 0xffffffffu;
        if (mb == wmax) {
#pragma unroll
            for (int j = 3; j >= 0; j--)
                if (__float_as_uint(dm[j]) == wmax) cand = base + (j << 8) + t;
        }
        unsigned widx = __reduce_min_sync(0xffffffffu, cand);
        if (lane == 0) { s_wval[w] = wmax; s_widx[w] = widx; }
        if (cand == widx && cand != 0xffffffffu) {     // unique owner thread
            int j = (int)((widx - base) >> 8);         // 0..3
            float a0, a1, b0v, b1v;
            upk2(xp[0], a0, a1); upk2(xp[1], b0v, b1v);
            s_wx[w] = (j < 2) ? ((j == 0) ? a0 : a1) : ((j == 2) ? b0v : b1v);
            upk2(yp[0], a0, a1); upk2(yp[1], b0v, b1v);
            s_wy[w] = (j < 2) ? ((j == 0) ? a0 : a1) : ((j == 2) ? b0v : b1v);
            upk2(zp[0], a0, a1); upk2(zp[1], b0v, b1v);
            s_wz[w] = (j < 2) ? ((j == 0) ? a0 : a1) : ((j == 2) ? b0v : b1v);
        }
        __syncthreads();   // bar1

        // ---- warp 0: CTA reduce, cluster exchange, global pick ----
        if (w == 0 && lane < 8) {
            unsigned lv = s_wval[lane];
            unsigned li = s_widx[lane];
            float lx = s_wx[lane], ly = s_wy[lane], lz = s_wz[lane];

            unsigned cmax = __reduce_max_sync(0xffu, lv);
            unsigned c2 = (lv == cmax) ? li : 0xffffffffu;
            unsigned cidx = __reduce_min_sync(0xffu, c2);

            unsigned obal = __ballot_sync(0xffu, c2 == cidx);
            int ol = __ffs(obal) - 1;
            float bx = __shfl_sync(0xffu, lx, ol);
            float by = __shfl_sync(0xffu, ly, ol);
            float bz = __shfl_sync(0xffu, lz, ol);

            unsigned long long key =
                ((unsigned long long)cmax << 32) | (unsigned)(8192u - cidx);

            // lane L delivers OUR candidate to CTA L's slot [buf][myrank]
            unsigned ck = smem_u32(&s_key[buf][rank]);
            unsigned cc = smem_u32(&s_cord[buf][rank]);
            unsigned rk = mapa_u32(ck, (unsigned)lane);
            unsigned rc = mapa_u32(cc, (unsigned)lane);
            st_cluster_v4(rc, bx, by, bz, 0.0f);
            st_cluster_rel_u64(rk, key);

            // poll my slot from src CTA = lane
            unsigned myslot = smem_u32(&s_key[buf][lane]);
            unsigned long long kk;
            do { kk = ld_acq_shared_u64(myslot); } while (kk == 0ULL);

            unsigned khi = (unsigned)(kk >> 32), klo = (unsigned)kk;
            unsigned ghi = __reduce_max_sync(0xffu, khi);
            unsigned gc = (khi == ghi) ? klo : 0u;
            unsigned glo = __reduce_max_sync(0xffu, gc);      // max(8192-idx)=min idx

            unsigned wb = __ballot_sync(0xffu, (khi == ghi) && (klo == glo));
            int wl = __ffs(wb) - 1;
            float4 cc4 = s_cord[buf][lane];
            float rx = __shfl_sync(0xffu, cc4.x, wl);
            float ry = __shfl_sync(0xffu, cc4.y, wl);
            float rz = __shfl_sync(0xffu, cc4.z, wl);

            s_key[buf2][lane] = 0ULL;       // reset local buffer for step s+2
            if (lane == 0) s_res = make_float4(rx, ry, rz, 0.0f);
        }
        __syncthreads();   // bar2

        float4 r = s_res;
        cx = r.x; cy = r.y; cz = r.z;
        if (rank == 0 && t == 0) {
            float* nz = new_xyz + ((size_t)b * NCTR + s) * 3;
            nz[0] = cx; nz[1] = cy; nz[2] = cz;
        }
    }
    CLUSTER_SYNC();
}

// =====================================================================
// 2) F0(b, j, o) = sum_c w0[o, 3+c] * features[b, c, j]
// =====================================================================
__global__ void __launch_bounds__(128)
f0_kernel(const float* __restrict__ features, const float* __restrict__ w0)
{
    __shared__ float w0t[64][64];   // w0t[c][o]
    const int tid = threadIdx.x;
    const int b = blockIdx.y;
    const int j = blockIdx.x * 128 + tid;

    for (int i = tid; i < 64 * 64; i += 128) {
        int c = i >> 6, o = i & 63;
        w0t[c][o] = w0[o * C0IN + 3 + c];
    }
    __syncthreads();

    float acc[64];
#pragma unroll
    for (int o = 0; o < 64; o++) acc[o] = 0.0f;

    for (int c = 0; c < 64; c++) {
        float fc = features[((size_t)b * 64 + c) * NPTS + j];
#pragma unroll
        for (int o4 = 0; o4 < 64; o4 += 4) {
            float4 wv = *(const float4*)&w0t[c][o4];
            acc[o4 + 0] = fmaf(wv.x, fc, acc[o4 + 0]);
            acc[o4 + 1] = fmaf(wv.y, fc, acc[o4 + 1]);
            acc[o4 + 2] = fmaf(wv.z, fc, acc[o4 + 2]);
            acc[o4 + 3] = fmaf(wv.w, fc, acc[o4 + 3]);
        }
    }

    float* op = g_F0 + ((size_t)b * NPTS + j) * 64;
#pragma unroll
    for (int o4 = 0; o4 < 64; o4 += 4) {
        float4 v = make_float4(acc[o4], acc[o4 + 1], acc[o4 + 2], acc[o4 + 3]);
        *(float4*)(op + o4) = v;
    }
}

// =====================================================================
// 3) Ball query
// =====================================================================
__global__ void __launch_bounds__(128)
ballq_kernel(const float* __restrict__ pos, const float* __restrict__ new_xyz)
{
    const int gid = blockIdx.x * 128 + threadIdx.x;
    const int b = gid >> 11;          // / 2048

    const float* cz = new_xyz + (size_t)gid * 3;
    const float cx = cz[0], cy = cz[1], czz = cz[2];
    const float* pb = pos + (size_t)b * NPTS * 3;
    int* out = g_ballidx + (size_t)gid * NSAMP;

    int cnt = 0;
    int first = 0;
    for (int j = 0; j < NPTS; j++) {
        float dx = pb[3 * j + 0] - cx;
        float dy = pb[3 * j + 1] - cy;
        float dz = pb[3 * j + 2] - czz;
        float d = fmaf(dz, dz, fmaf(dy, dy, dx * dx));
        if (d < R2) {
            if (cnt == 0) first = j;
            out[cnt++] = j;
            if (cnt == NSAMP) break;
        }
    }
    for (int k = cnt; k < NSAMP; k++) out[k] = first;
}

// =====================================================================
// 4) Fused grouped MLP + max pool: 512 threads, 8 centers (256 rows)
//    per block. f32x2 GEMM cores. 16 warps -> 4/SMSP latency hiding.
// =====================================================================
#define MLPT 512
#define ROWS 256
#define XROW 260
#define SMEM_FLOATS (4096 + 8192 + 64*XROW + 64*XROW + 256 + 64 + 128)

__global__ void __launch_bounds__(MLPT, 1)
fused_mlp_kernel(const float* __restrict__ pos,
                 const float* __restrict__ new_xyz,
                 const float* __restrict__ w0, const float* __restrict__ b0,
                 const float* __restrict__ w1, const float* __restrict__ b1,
                 const float* __restrict__ w2, const float* __restrict__ b2,
                 float* __restrict__ out_feat)
{
    extern __shared__ float sm[];
    float* sW1 = sm;                       // [c][o] 64x64
    float* sW2 = sm + 4096;                // [c][o] 64x128
    float* sX0 = sm + 12288;               // [c][m] 64 x XROW
    float* sX1 = sm + 12288 + 64 * XROW;   // [c][m] 64 x XROW
    float4* sWXB = (float4*)(sm + 12288 + 128 * XROW);   // 64 x {w0x,w0y,w0z,b0}
    float* sB1 = sm + 12288 + 128 * XROW + 256;
    float* sB2 = sB1 + 64;

    const int tid = threadIdx.x;
    const int b = blockIdx.x >> 8;
    const int s0 = (blockIdx.x & 255) * 8;

    // ---- load weights (transposed) ----
    for (int i = tid; i < 4096; i += MLPT) {
        int c = i >> 6, o = i & 63;
        sW1[c * 64 + o] = w1[o * 64 + c];
    }
    for (int i = tid; i < 8192; i += MLPT) {
        int c = i >> 7, o = i & 127;
        sW2[c * 128 + o] = w2[o * 64 + c];
    }
    if (tid < 64) {
        sWXB[tid] = make_float4(w0[tid * C0IN + 0], w0[tid * C0IN + 1],
                                w0[tid * C0IN + 2], b0[tid]);
        sB1[tid] = b1[tid];
    }
    if (tid < 128) sB2[tid] = b2[tid];
    __syncthreads();

    // ---- phase A: build X0 (layer0 output), 256 rows x 64 ch ----
    {
        const int r = tid >> 1;            // row 0..255
        const int h = tid & 1;
        const int o0 = h * 32;
        const int ci = r >> 5, k = r & 31;
        const int sg = s0 + ci;
        const int j = g_ballidx[(((size_t)b * NCTR + sg) << 5) + k];

        const float* pp = pos + ((size_t)b * NPTS + j) * 3;
        const float* cz = new_xyz + ((size_t)b * NCTR + sg) * 3;
        float rx = pp[0] - cz[0];
        float ry = pp[1] - cz[1];
        float rz = pp[2] - cz[2];
        const float* fp = g_F0 + ((size_t)b * NPTS + j) * 64 + o0;

#pragma unroll
        for (int o4 = 0; o4 < 32; o4 += 4) {
            float4 f = *(const float4*)(fp + o4);
            float fv[4] = { f.x, f.y, f.z, f.w };
#pragma unroll
            for (int i = 0; i < 4; i++) {
                float4 wb = sWXB[o0 + o4 + i];
                float v = fv[i] + wb.x * rx + wb.y * ry + wb.z * rz + wb.w;
                sX0[(o0 + o4 + i) * XROW + r] = fmaxf(v, 0.0f);
            }
        }
    }
    __syncthreads();

    const int tm = tid & 63, tn = tid >> 6;      // tn constant within a warp
    const int m0 = tm * 4;

    // ---- GEMM1: X1 = relu(X0 @ W1^T + b1), 256x64, f32x2 ----
    {
        const int n0 = tn * 8;
        unsigned long long acc2[16];
#pragma unroll
        for (int i = 0; i < 16; i++) acc2[i] = 0ULL;

#pragma unroll 8
        for (int c = 0; c < 64; c++) {
            float4 a  = *(const float4*)&sX0[c * XROW + m0];
            float4 bA = *(const float4*)&sW1[c * 64 + n0];
            float4 bB = *(const float4*)&sW1[c * 64 + n0 + 4];
            unsigned long long bp[4] = { pk2(bA.x, bA.y), pk2(bA.z, bA.w),
                                         pk2(bB.x, bB.y), pk2(bB.z, bB.w) };
            unsigned long long ap[4] = { pkb(a.x), pkb(a.y), pkb(a.z), pkb(a.w) };
#pragma unroll
            for (int i = 0; i < 4; i++)
#pragma unroll
                for (int jp = 0; jp < 4; jp++)
                    F2FMA(acc2[i * 4 + jp], ap[i], bp[jp], acc2[i * 4 + jp]);
        }

#pragma unroll
        for (int jp = 0; jp < 4; jp++) {
            float lo[4], hi[4];
#pragma unroll
            for (int i = 0; i < 4; i++) upk2(acc2[i * 4 + jp], lo[i], hi[i]);
            float bb0 = sB1[n0 + 2 * jp], bb1 = sB1[n0 + 2 * jp + 1];
            float4 v0, v1;
            v0.x = fmaxf(lo[0] + bb0, 0.0f); v0.y = fmaxf(lo[1] + bb0, 0.0f);
            v0.z = fmaxf(lo[2] + bb0, 0.0f); v0.w = fmaxf(lo[3] + bb0, 0.0f);
            v1.x = fmaxf(hi[0] + bb1, 0.0f); v1.y = fmaxf(hi[1] + bb1, 0.0f);
            v1.z = fmaxf(hi[2] + bb1, 0.0f); v1.w = fmaxf(hi[3] + bb1, 0.0f);
            *(float4*)&sX1[(n0 + 2 * jp)     * XROW + m0] = v0;
            *(float4*)&sX1[(n0 + 2 * jp + 1) * XROW + m0] = v1;
        }
    }
    __syncthreads();

    // ---- GEMM2: Y = X1 @ W2^T, 256x128, f32x2, fold max+bias+relu ----
    {
        const int n2 = tn * 16;
        unsigned long long acc2[32];
#pragma unroll
        for (int i = 0; i < 32; i++) acc2[i] = 0ULL;

#pragma unroll 4
        for (int c = 0; c < 64; c++) {
            float4 a = *(const float4*)&sX1[c * XROW + m0];
            unsigned long long ap[4] = { pkb(a.x), pkb(a.y), pkb(a.z), pkb(a.w) };
            unsigned long long bp[8];
#pragma unroll
            for (int q = 0; q < 4; q++) {
                float4 bb = *(const float4*)&sW2[c * 128 + n2 + 4 * q];
                bp[2 * q]     = pk2(bb.x, bb.y);
                bp[2 * q + 1] = pk2(bb.z, bb.w);
            }
#pragma unroll
            for (int i = 0; i < 4; i++)
#pragma unroll
                for (int jp = 0; jp < 8; jp++)
                    F2FMA(acc2[i * 8 + jp], ap[i], bp[jp], acc2[i * 8 + jp]);
        }

        const int center = tm >> 3;   // 8 centers per block
#pragma unroll
        for (int jp = 0; jp < 8; jp++) {
            float lo[4], hi[4];
#pragma unroll
            for (int i = 0; i < 4; i++) upk2(acc2[i * 8 + jp], lo[i], hi[i]);
            float vlo = fmaxf(fmaxf(lo[0], lo[1]), fmaxf(lo[2], lo[3]));
            float vhi = fmaxf(fmaxf(hi[0], hi[1]), fmaxf(hi[2], hi[3]));
            vlo = fmaxf(vlo, __shfl_xor_sync(0xffffffffu, vlo, 1));
            vhi = fmaxf(vhi, __shfl_xor_sync(0xffffffffu, vhi, 1));
            vlo = fmaxf(vlo, __shfl_xor_sync(0xffffffffu, vlo, 2));
            vhi = fmaxf(vhi, __shfl_xor_sync(0xffffffffu, vhi, 2));
            vlo = fmaxf(vlo, __shfl_xor_sync(0xffffffffu, vlo, 4));
            vhi = fmaxf(vhi, __shfl_xor_sync(0xffffffffu, vhi, 4));
            if ((tm & 7) == 0) {
                int n = n2 + 2 * jp;
                out_feat[((size_t)b * C2 + n)     * NCTR + (s0 + center)] =
                    fmaxf(vlo + sB2[n], 0.0f);
                out_feat[((size_t)b * C2 + n + 1) * NCTR + (s0 + center)] =
                    fmaxf(vhi + sB2[n + 1], 0.0f);
            }
        }
    }
}

// =====================================================================
extern "C" void kernel_launch(void* const* d_in, const int* in_sizes, int n_in,
                              void* d_out, int out_size)
{
    const float* pos      = (const float*)d_in[0];
    const float* features = (const float*)d_in[1];
    const float* w0       = (const float*)d_in[2];
    const float* b0       = (const float*)d_in[3];
    const float* w1       = (const float*)d_in[4];
    const float* b1       = (const float*)d_in[5];
    const float* w2       = (const float*)d_in[6];
    const float* b2       = (const float*)d_in[7];

    float* out = (float*)d_out;
    float* new_xyz  = out;                               // (8, 2048, 3)
    float* out_feat = out + (size_t)BATCH * NCTR * 3;    // (8, 128, 2048)

    fps_kernel<<<BATCH * FPS_CLUSTER, FPS_THREADS>>>(pos, new_xyz);
    f0_kernel<<<dim3(NPTS / 128, BATCH), 128>>>(features, w0);
    ballq_kernel<<<(BATCH * NCTR) / 128, 128>>>(pos, new_xyz);

    cudaFuncSetAttribute(fused_mlp_kernel,
                         cudaFuncAttributeMaxDynamicSharedMemorySize,
                         SMEM_FLOATS * sizeof(float));
    fused_mlp_kernel<<<BATCH * NCTR / 8, MLPT, SMEM_FLOATS * sizeof(float)>>>(
        pos, new_xyz, w0, b0, w1, b1, w2, b2, out_feat);
}

// round 4
// speedup vs baseline: 1.9046x; 1.9046x over previous
#include <cuda_runtime.h>
#include <cuda_bf16.h>
#include <cstdint>

#define BATCH 8
#define NPTS  8192
#define NCTR  2048          // NPTS * 0.25
#define NSAMP 32
#define C0IN  67
#define C0    64
#define C1    64
#define C2    128
#define R2    0.25f         // radius^2

// ---------------- scratch (device globals; no allocation allowed) ----------------
__device__ int   g_ballidx[BATCH * NCTR * NSAMP];            // 2 MB
__device__ float g_F0[(size_t)BATCH * NPTS * C0];            // 16 MB, layout (b, j, o)

// ---------------- f32x2 packed helpers ----------------
__device__ __forceinline__ unsigned long long pk2(float lo, float hi) {
    unsigned long long r;
    asm("mov.b64 %0, {%1, %2};" : "=l"(r) : "f"(lo), "f"(hi));
    return r;
}
__device__ __forceinline__ unsigned long long pkb(float v) { return pk2(v, v); }
__device__ __forceinline__ void upk2(unsigned long long v, float& lo, float& hi) {
    asm("mov.b64 {%0, %1}, %2;" : "=f"(lo), "=f"(hi) : "l"(v));
}
#define F2FMA(d, a, b, c) asm("fma.rn.f32x2 %0, %1, %2, %3;" : "=l"(d) : "l"(a), "l"(b), "l"(c))
#define F2ADD(d, a, b)    asm("add.rn.f32x2 %0, %1, %2;"     : "=l"(d) : "l"(a), "l"(b))
#define F2MUL(d, a, b)    asm("mul.rn.f32x2 %0, %1, %2;"     : "=l"(d) : "l"(a), "l"(b))

// =====================================================================
// 1) FPS: one CTA per batch, 512 threads, 16 pts/thread (f32x2 packed).
//    ONE barrier per step; parity-double-buffered per-warp (val, 8192-idx)
//    pairs; every warp redundantly reduces the 16 warp results.
// =====================================================================
__global__ void __launch_bounds__(512, 1)
fps_kernel(const float* __restrict__ pos, float* __restrict__ new_xyz)
{
    const int b = blockIdx.x;
    const int t = threadIdx.x;
    const int lane = t & 31, w = t >> 5;
    const float* pb = pos + (size_t)b * NPTS * 3;

    unsigned long long xp[8], yp[8], zp[8];
    float dm[16];
#pragma unroll
    for (int k = 0; k < 8; k++) {
        int p0 = t + (2 * k) * 512;
        int p1 = p0 + 512;
        xp[k] = pk2(pb[3 * p0 + 0], pb[3 * p1 + 0]);
        yp[k] = pk2(pb[3 * p0 + 1], pb[3 * p1 + 1]);
        zp[k] = pk2(pb[3 * p0 + 2], pb[3 * p1 + 2]);
        dm[2 * k] = 1e10f; dm[2 * k + 1] = 1e10f;
    }

    __shared__ unsigned s_vhi[2][16];    // [parity][warp] distance bits
    __shared__ unsigned s_vlo[2][16];    // [parity][warp] 8192 - idx

    float cx = pb[0], cy = pb[1], cz = pb[2];
    if (t == 0) {
        float* nz = new_xyz + (size_t)b * NCTR * 3;
        nz[0] = cx; nz[1] = cy; nz[2] = cz;
    }

    for (int s = 1; s < NCTR; ++s) {
        const int buf = s & 1;

        // ---- distance update (f32x2) + per-thread max ----
        const unsigned long long nx  = pkb(-cx);
        const unsigned long long ny  = pkb(-cy);
        const unsigned long long nzp = pkb(-cz);
        float m = 0.0f;
#pragma unroll
        for (int k = 0; k < 8; k++) {
            unsigned long long dx, dy, dz, sq;
            F2ADD(dx, xp[k], nx);
            F2ADD(dy, yp[k], ny);
            F2ADD(dz, zp[k], nzp);
            F2MUL(sq, dx, dx);
            F2FMA(sq, dy, dy, sq);
            F2FMA(sq, dz, dz, sq);          // == scalar fmaf(dz,dz,fmaf(dy,dy,dx*dx))
            float lo, hi; upk2(sq, lo, hi);
            dm[2 * k]     = fminf(dm[2 * k], lo);
            dm[2 * k + 1] = fminf(dm[2 * k + 1], hi);
            m = fmaxf(m, dm[2 * k]);
            m = fmaxf(m, dm[2 * k + 1]);
        }

        // ---- warp reduce: max value, min index on ties ----
        unsigned mb = __float_as_uint(m);            // d >= 0: order-preserving
        unsigned wmax = __reduce_max_sync(0xffffffffu, mb);
        unsigned cand = 0xffffffffu;
        if (mb == wmax) {
#pragma unroll
            for (int j = 15; j >= 0; j--)
                if (__float_as_uint(dm[j]) == wmax) cand = (unsigned)((j << 9) + t);
        }
        unsigned widx = __reduce_min_sync(0xffffffffu, cand);
        if (lane == 0) {
            s_vhi[buf][w] = wmax;
            s_vlo[buf][w] = 8192u - widx;            // larger = smaller index
        }
        __syncthreads();                             // the ONLY barrier per step

        // ---- every warp redundantly reduces the 16 warp pairs ----
        unsigned v   = (lane < 16) ? s_vhi[buf][lane] : 0u;
        unsigned ghi = __reduce_max_sync(0xffffffffu, v);
        unsigned lo2 = (lane < 16 && v == ghi) ? s_vlo[buf][lane] : 0u;
        unsigned glo = __reduce_max_sync(0xffffffffu, lo2);
        unsigned gidx = 8192u - glo;

        const float* pp = pb + 3 * (size_t)gidx;     // broadcast LDG, L1-hit
        cx = pp[0]; cy = pp[1]; cz = pp[2];
        if (t == 0) {
            float* nz = new_xyz + ((size_t)b * NCTR + s) * 3;
            nz[0] = cx; nz[1] = cy; nz[2] = cz;
        }
    }
}

// =====================================================================
// 2) F0(b, j, o) = sum_c w0[o, 3+c] * features[b, c, j]
// =====================================================================
__global__ void __launch_bounds__(128)
f0_kernel(const float* __restrict__ features, const float* __restrict__ w0)
{
    __shared__ float w0t[64][64];   // w0t[c][o]
    const int tid = threadIdx.x;
    const int b = blockIdx.y;
    const int j = blockIdx.x * 128 + tid;

    for (int i = tid; i < 64 * 64; i += 128) {
        int c = i >> 6, o = i & 63;
        w0t[c][o] = w0[o * C0IN + 3 + c];
    }
    __syncthreads();

    float acc[64];
#pragma unroll
    for (int o = 0; o < 64; o++) acc[o] = 0.0f;

    for (int c = 0; c < 64; c++) {
        float fc = features[((size_t)b * 64 + c) * NPTS + j];
#pragma unroll
        for (int o4 = 0; o4 < 64; o4 += 4) {
            float4 wv = *(const float4*)&w0t[c][o4];
            acc[o4 + 0] = fmaf(wv.x, fc, acc[o4 + 0]);
            acc[o4 + 1] = fmaf(wv.y, fc, acc[o4 + 1]);
            acc[o4 + 2] = fmaf(wv.z, fc, acc[o4 + 2]);
            acc[o4 + 3] = fmaf(wv.w, fc, acc[o4 + 3]);
        }
    }

    float* op = g_F0 + ((size_t)b * NPTS + j) * 64;
#pragma unroll
    for (int o4 = 0; o4 < 64; o4 += 4) {
        float4 v = make_float4(acc[o4], acc[o4 + 1], acc[o4 + 2], acc[o4 + 3]);
        *(float4*)(op + o4) = v;
    }
}

// =====================================================================
// 3) Ball query
// =====================================================================
__global__ void __launch_bounds__(128)
ballq_kernel(const float* __restrict__ pos, const float* __restrict__ new_xyz)
{
    const int gid = blockIdx.x * 128 + threadIdx.x;
    const int b = gid >> 11;          // / 2048

    const float* cz = new_xyz + (size_t)gid * 3;
    const float cx = cz[0], cy = cz[1], czz = cz[2];
    const float* pb = pos + (size_t)b * NPTS * 3;
    int* out = g_ballidx + (size_t)gid * NSAMP;

    int cnt = 0;
    int first = 0;
    for (int j = 0; j < NPTS; j++) {
        float dx = pb[3 * j + 0] - cx;
        float dy = pb[3 * j + 1] - cy;
        float dz = pb[3 * j + 2] - czz;
        float d = fmaf(dz, dz, fmaf(dy, dy, dx * dx));
        if (d < R2) {
            if (cnt == 0) first = j;
            out[cnt++] = j;
            if (cnt == NSAMP) break;
        }
    }
    for (int k = cnt; k < NSAMP; k++) out[k] = first;
}

// =====================================================================
// 4) Fused grouped MLP + max pool: 512 threads, 8 centers (256 rows)
//    per block. f32x2 GEMM cores. (unchanged from round 3: 383us)
// =====================================================================
#define MLPT 512
#define XROW 260
#define SMEM_FLOATS (4096 + 8192 + 64*XROW + 64*XROW + 256 + 64 + 128)

__global__ void __launch_bounds__(MLPT, 1)
fused_mlp_kernel(const float* __restrict__ pos,
                 const float* __restrict__ new_xyz,
                 const float* __restrict__ w0, const float* __restrict__ b0,
                 const float* __restrict__ w1, const float* __restrict__ b1,
                 const float* __restrict__ w2, const float* __restrict__ b2,
                 float* __restrict__ out_feat)
{
    extern __shared__ float sm[];
    float* sW1 = sm;                       // [c][o] 64x64
    float* sW2 = sm + 4096;                // [c][o] 64x128
    float* sX0 = sm + 12288;               // [c][m] 64 x XROW
    float* sX1 = sm + 12288 + 64 * XROW;   // [c][m] 64 x XROW
    float4* sWXB = (float4*)(sm + 12288 + 128 * XROW);   // 64 x {w0x,w0y,w0z,b0}
    float* sB1 = sm + 12288 + 128 * XROW + 256;
    float* sB2 = sB1 + 64;

    const int tid = threadIdx.x;
    const int b = blockIdx.x >> 8;
    const int s0 = (blockIdx.x & 255) * 8;

    // ---- load weights (transposed) ----
    for (int i = tid; i < 4096; i += MLPT) {
        int c = i >> 6, o = i & 63;
        sW1[c * 64 + o] = w1[o * 64 + c];
    }
    for (int i = tid; i < 8192; i += MLPT) {
        int c = i >> 7, o = i & 127;
        sW2[c * 128 + o] = w2[o * 64 + c];
    }
    if (tid < 64) {
        sWXB[tid] = make_float4(w0[tid * C0IN + 0], w0[tid * C0IN + 1],
                                w0[tid * C0IN + 2], b0[tid]);
        sB1[tid] = b1[tid];
    }
    if (tid < 128) sB2[tid] = b2[tid];
    __syncthreads();

    // ---- phase A: build X0 (layer0 output), 256 rows x 64 ch ----
    {
        const int r = tid >> 1;            // row 0..255
        const int h = tid & 1;
        const int o0 = h * 32;
        const int ci = r >> 5, k = r & 31;
        const int sg = s0 + ci;
        const int j = g_ballidx[(((size_t)b * NCTR + sg) << 5) + k];

        const float* pp = pos + ((size_t)b * NPTS + j) * 3;
        const float* cz = new_xyz + ((size_t)b * NCTR + sg) * 3;
        float rx = pp[0] - cz[0];
        float ry = pp[1] - cz[1];
        float rz = pp[2] - cz[2];
        const float* fp = g_F0 + ((size_t)b * NPTS + j) * 64 + o0;

#pragma unroll
        for (int o4 = 0; o4 < 32; o4 += 4) {
            float4 f = *(const float4*)(fp + o4);
            float fv[4] = { f.x, f.y, f.z, f.w };
#pragma unroll
            for (int i = 0; i < 4; i++) {
                float4 wb = sWXB[o0 + o4 + i];
                float v = fv[i] + wb.x * rx + wb.y * ry + wb.z * rz + wb.w;
                sX0[(o0 + o4 + i) * XROW + r] = fmaxf(v, 0.0f);
            }
        }
    }
    __syncthreads();

    const int tm = tid & 63, tn = tid >> 6;      // tn constant within a warp
    const int m0 = tm * 4;

    // ---- GEMM1: X1 = relu(X0 @ W1^T + b1), 256x64, f32x2 ----
    {
        const int n0 = tn * 8;
        unsigned long long acc2[16];
#pragma unroll
        for (int i = 0; i < 16; i++) acc2[i] = 0ULL;

#pragma unroll 8
        for (int c = 0; c < 64; c++) {
            float4 a  = *(const float4*)&sX0[c * XROW + m0];
            float4 bA = *(const float4*)&sW1[c * 64 + n0];
            float4 bB = *(const float4*)&sW1[c * 64 + n0 + 4];
            unsigned long long bp[4] = { pk2(bA.x, bA.y), pk2(bA.z, bA.w),
                                         pk2(bB.x, bB.y), pk2(bB.z, bB.w) };
            unsigned long long ap[4] = { pkb(a.x), pkb(a.y), pkb(a.z), pkb(a.w) };
#pragma unroll
            for (int i = 0; i < 4; i++)
#pragma unroll
                for (int jp = 0; jp < 4; jp++)
                    F2FMA(acc2[i * 4 + jp], ap[i], bp[jp], acc2[i * 4 + jp]);
        }

#pragma unroll
        for (int jp = 0; jp < 4; jp++) {
            float lo[4], hi[4];
#pragma unroll
            for (int i = 0; i < 4; i++) upk2(acc2[i * 4 + jp], lo[i], hi[i]);
            float bb0 = sB1[n0 + 2 * jp], bb1 = sB1[n0 + 2 * jp + 1];
            float4 v0, v1;
            v0.x = fmaxf(lo[0] + bb0, 0.0f); v0.y = fmaxf(lo[1] + bb0, 0.0f);
            v0.z = fmaxf(lo[2] + bb0, 0.0f); v0.w = fmaxf(lo[3] + bb0, 0.0f);
            v1.x = fmaxf(hi[0] + bb1, 0.0f); v1.y = fmaxf(hi[1] + bb1, 0.0f);
            v1.z = fmaxf(hi[2] + bb1, 0.0f); v1.w = fmaxf(hi[3] + bb1, 0.0f);
            *(float4*)&sX1[(n0 + 2 * jp)     * XROW + m0] = v0;
            *(float4*)&sX1[(n0 + 2 * jp + 1) * XROW + m0] = v1;
        }
    }
    __syncthreads();

    // ---- GEMM2: Y = X1 @ W2^T, 256x128, f32x2, fold max+bias+relu ----
    {
        const int n2 = tn * 16;
        unsigned long long acc2[32];
#pragma unroll
        for (int i = 0; i < 32; i++) acc2[i] = 0ULL;

#pragma unroll 4
        for (int c = 0; c < 64; c++) {
            float4 a = *(const float4*)&sX1[c * XROW + m0];
            unsigned long long ap[4] = { pkb(a.x), pkb(a.y), pkb(a.z), pkb(a.w) };
            unsigned long long bp[8];
#pragma unroll
            for (int q = 0; q < 4; q++) {
                float4 bb = *(const float4*)&sW2[c * 128 + n2 + 4 * q];
                bp[2 * q]     = pk2(bb.x, bb.y);
                bp[2 * q + 1] = pk2(bb.z, bb.w);
            }
#pragma unroll
            for (int i = 0; i < 4; i++)
#pragma unroll
                for (int jp = 0; jp < 8; jp++)
                    F2FMA(acc2[i * 8 + jp], ap[i], bp[jp], acc2[i * 8 + jp]);
        }

        const int center = tm >> 3;   // 8 centers per block
#pragma unroll
        for (int jp = 0; jp < 8; jp++) {
            float lo[4], hi[4];
#pragma unroll
            for (int i = 0; i < 4; i++) upk2(acc2[i * 8 + jp], lo[i], hi[i]);
            float vlo = fmaxf(fmaxf(lo[0], lo[1]), fmaxf(lo[2], lo[3]));
            float vhi = fmaxf(fmaxf(hi[0], hi[1]), fmaxf(hi[2], hi[3]));
            vlo = fmaxf(vlo, __shfl_xor_sync(0xffffffffu, vlo, 1));
            vhi = fmaxf(vhi, __shfl_xor_sync(0xffffffffu, vhi, 1));
            vlo = fmaxf(vlo, __shfl_xor_sync(0xffffffffu, vlo, 2));
            vhi = fmaxf(vhi, __shfl_xor_sync(0xffffffffu, vhi, 2));
            vlo = fmaxf(vlo, __shfl_xor_sync(0xffffffffu, vlo, 4));
            vhi = fmaxf(vhi, __shfl_xor_sync(0xffffffffu, vhi, 4));
            if ((tm & 7) == 0) {
                int n = n2 + 2 * jp;
                out_feat[((size_t)b * C2 + n)     * NCTR + (s0 + center)] =
                    fmaxf(vlo + sB2[n], 0.0f);
                out_feat[((size_t)b * C2 + n + 1) * NCTR + (s0 + center)] =
                    fmaxf(vhi + sB2[n + 1], 0.0f);
            }
        }
    }
}

// =====================================================================
extern "C" void kernel_launch(void* const* d_in, const int* in_sizes, int n_in,
                              void* d_out, int out_size)
{
    const float* pos      = (const float*)d_in[0];
    const float* features = (const float*)d_in[1];
    const float* w0       = (const float*)d_in[2];
    const float* b0       = (const float*)d_in[3];
    const float* w1       = (const float*)d_in[4];
    const float* b1       = (const float*)d_in[5];
    const float* w2       = (const float*)d_in[6];
    const float* b2       = (const float*)d_in[7];

    float* out = (float*)d_out;
    float* new_xyz  = out;                               // (8, 2048, 3)
    float* out_feat = out + (size_t)BATCH * NCTR * 3;    // (8, 128, 2048)

    fps_kernel<<<BATCH, 512>>>(pos, new_xyz);
    f0_kernel<<<dim3(NPTS / 128, BATCH), 128>>>(features, w0);
    ballq_kernel<<<(BATCH * NCTR) / 128, 128>>>(pos, new_xyz);

    cudaFuncSetAttribute(fused_mlp_kernel,
                         cudaFuncAttributeMaxDynamicSharedMemorySize,
                         SMEM_FLOATS * sizeof(float));
    fused_mlp_kernel<<<BATCH * NCTR / 8, MLPT, SMEM_FLOATS * sizeof(float)>>>(
        pos, new_xyz, w0, b0, w1, b1, w2, b2, out_feat);
}